// round 10
// baseline (speedup 1.0000x reference)
#include <cuda_runtime.h>
#include <cuda_fp16.h>
#include <cstdint>
#include <cstddef>

#define NSEQ 512
#define HID  384
#define EOUT 128

// ---------------------------------------------------------------------------
// device-global scratch (no allocations allowed)
// ---------------------------------------------------------------------------
__device__ float g_nb [NSEQ * 128];
__device__ __align__(16) float g_p0i[NSEQ * HID];
__device__ __align__(16) float g_p0j[NSEQ * HID];
__device__ __align__(16) float g_pfi[NSEQ * EOUT];
__device__ __align__(16) float g_pfj[NSEQ * EOUT];
// transposed fp16 weights, [N][K] row-major
__device__ __align__(16) __half g_w0h[HID  * 128];   // W0top^T  [384][128]
__device__ __align__(16) __half g_wrh[EOUT * 128];   // Wf_top^T [128][128]
__device__ __align__(16) __half g_w1h[HID  * HID];   // W1^T     [384][384]
__device__ __align__(16) __half g_wfh[EOUT * HID];   // Wf^T     [128][384]

// ---------------------------------------------------------------------------
// helpers (baseline PTX only: mma.sync / ldmatrix / cp.async)
// ---------------------------------------------------------------------------
__device__ __forceinline__ uint32_t smem_u32(const void* p) {
    uint32_t a;
    asm("{ .reg .u64 t; cvta.to.shared.u64 t, %1; cvt.u32.u64 %0, t; }"
        : "=r"(a) : "l"(p));
    return a;
}
__device__ __forceinline__ void cpa16(uint32_t dst, const void* src) {
    asm volatile("cp.async.cg.shared.global [%0], [%1], 16;"
                 :: "r"(dst), "l"(src));
}
#define CP_COMMIT() asm volatile("cp.async.commit_group;" ::: "memory")
#define CP_WAIT(n)  asm volatile("cp.async.wait_group %0;" :: "n"(n) : "memory")

__device__ __forceinline__ void ldmx4(uint32_t* r, uint32_t a) {
    asm volatile("ldmatrix.sync.aligned.m8n8.x4.shared.b16 {%0,%1,%2,%3}, [%4];"
                 : "=r"(r[0]), "=r"(r[1]), "=r"(r[2]), "=r"(r[3]) : "r"(a));
}
__device__ __forceinline__ void mma16(float* c, const uint32_t* a, const uint32_t* b) {
    asm volatile("mma.sync.aligned.m16n8k16.row.col.f32.f16.f16.f32 "
                 "{%0,%1,%2,%3},{%4,%5,%6,%7},{%8,%9},{%0,%1,%2,%3};"
                 : "+f"(c[0]), "+f"(c[1]), "+f"(c[2]), "+f"(c[3])
                 : "r"(a[0]), "r"(a[1]), "r"(a[2]), "r"(a[3]),
                   "r"(b[0]), "r"(b[1]));
}

// ---------------------------------------------------------------------------
// prep kernels
// ---------------------------------------------------------------------------
__global__ void nb_kernel(const float* __restrict__ node,
                          const float* __restrict__ w_init,
                          const float* __restrict__ b_init) {
    __shared__ float xs[256];
    int i = blockIdx.x, t = threadIdx.x;   // 128 threads
    xs[t]       = node[i * 256 + t];
    xs[t + 128] = node[i * 256 + 128 + t];
    __syncthreads();
    float acc = b_init[t];
#pragma unroll 8
    for (int k = 0; k < 256; k++) acc += xs[k] * w_init[k * 128 + t];
    g_nb[i * 128 + t] = acc;
}

__global__ void pre_kernel(const float* __restrict__ w_t0,
                           const float* __restrict__ b_t0,
                           const float* __restrict__ w_fin,
                           const float* __restrict__ b_fin) {
    __shared__ float nbs[128];
    int i = blockIdx.x, t = threadIdx.x;   // 384 threads
    if (t < 128) nbs[t] = g_nb[i * 128 + t];
    __syncthreads();
    float a0 = b_t0[t], a1 = 0.f;
#pragma unroll 8
    for (int k = 0; k < 128; k++) {
        float v = nbs[k];
        a0 += v * w_t0[(128 + k) * HID + t];
        a1 += v * w_t0[(256 + k) * HID + t];
    }
    g_p0i[i * HID + t] = a0;
    g_p0j[i * HID + t] = a1;
    if (t < 128) {
        float f0 = b_fin[t], f1 = 0.f;
#pragma unroll 8
        for (int k = 0; k < 128; k++) {
            float v = nbs[k];
            f0 += v * w_fin[(128 + k) * EOUT + t];
            f1 += v * w_fin[(256 + k) * EOUT + t];
        }
        g_pfi[i * EOUT + t] = f0;
        g_pfj[i * EOUT + t] = f1;
    }
}

// transpose + fp16-convert weights: dst[n][k] = (half)W[k][n]
__global__ void packh_kernel(const float* __restrict__ w_t0,
                             const float* __restrict__ w_t1,
                             const float* __restrict__ w_fin) {
    const int T0 = HID * 128, T1 = EOUT * 128, T2 = HID * HID, T3 = EOUT * HID;
    for (int x = blockIdx.x * blockDim.x + threadIdx.x; x < T0 + T1 + T2 + T3;
         x += gridDim.x * blockDim.x) {
        if (x < T0) {
            int n = x >> 7, k = x & 127;
            g_w0h[x] = __float2half(w_t0[k * HID + n]);
        } else if (x < T0 + T1) {
            int y = x - T0, n = y >> 7, k = y & 127;
            g_wrh[y] = __float2half(w_fin[k * EOUT + n]);
        } else if (x < T0 + T1 + T2) {
            int y = x - T0 - T1, n = y / HID, k = y - n * HID;
            g_w1h[y] = __float2half(w_t1[k * HID + n]);
        } else {
            int y = x - T0 - T1 - T2, n = y / HID, k = y - n * HID;
            g_wfh[y] = __float2half(w_fin[k * EOUT + n]);
        }
    }
}

// ---------------------------------------------------------------------------
// fused kernel: M=64 rows per CTA, 512 threads = 16 warps (2 rowg x 8 colg)
// SMEM (bytes):
//   t0  [64][392]h @ 0        (50176)
//   rs  [64][392]h @ 50176    (50176)
//   E   [64][136]h @ 100352   (17408)   } o_buf [64][132]f @100352 (33792)
//   R   [64][136]h @ 117760   (17408)   }   overlays E+R after both dead
//   B0  [384][56]h @ 135168   (43008)
//   B1  [384][56]h @ 178176   (43008)
// total 221184
// ---------------------------------------------------------------------------
#define T0_OFF 0
#define RS_OFF 50176
#define E_OFF  100352
#define R_OFF  117760
#define O_OFF  100352
#define B0_OFF 135168
#define B1_OFF 178176
#define SMEMSZ 221184
#define LDB    56
#define NTHR   512

__device__ __forceinline__ void stage(const __half* __restrict__ g, int K,
                                      int kc, int klen8, int nrows,
                                      uint32_t dst, int tid) {
    const int tot = nrows * klen8;
    for (int v = tid; v < tot; v += NTHR) {
        int n = v / klen8, c = v - n * klen8;
        cpa16(dst + (uint32_t)(n * LDB + c * 8) * 2,
              g + (size_t)n * K + kc + c * 8);
    }
}

// acc layout: acc[mg*NT + ng][4], mg in {0,1} (m16 groups), ng in [0,NT)
template <int NT, int KLEN, int NCH>
__device__ __forceinline__ void run_gemm(const __half* __restrict__ gB, int K,
                                         int nrows, uint32_t aBase, int lda,
                                         int n0, uint32_t bb0, uint32_t bb1,
                                         float (*acc)[4], int tid, int lane) {
    constexpr int K8 = KLEN >> 3;
    const uint32_t aro = (lane & 7) + (((lane >> 3) & 1) << 3);  // A row off
    const uint32_t ako = (lane >> 4) << 3;                       // A k off
    const uint32_t bro = (lane & 7) + ((lane >> 4) << 3);        // B row off
    const uint32_t bko = ((lane >> 3) & 1) << 3;                 // B k off

    stage(gB, K, 0, K8, nrows, bb0, tid);
    CP_COMMIT();
#pragma unroll 1
    for (int c = 0; c < NCH; c++) {
        if (c + 1 < NCH) {
            stage(gB, K, (c + 1) * KLEN, K8, nrows, (c & 1) ? bb0 : bb1, tid);
            CP_COMMIT();
            CP_WAIT(1);
        } else {
            CP_WAIT(0);
        }
        __syncthreads();
        const uint32_t bb = (c & 1) ? bb1 : bb0;
#pragma unroll
        for (int kk = 0; kk < KLEN; kk += 16) {
            uint32_t af[2][4];
#pragma unroll
            for (int mg = 0; mg < 2; mg++)
                ldmx4(af[mg], aBase + 2u * (((mg << 4) + aro) * lda +
                                            c * KLEN + kk + ako));
#pragma unroll
            for (int np = 0; np < NT / 2; np++) {
                uint32_t bf[4];
                ldmx4(bf, bb + 2u * ((n0 + (np << 4) + bro) * LDB + kk + bko));
#pragma unroll
                for (int mg = 0; mg < 2; mg++) {
                    mma16(acc[mg * NT + 2 * np],     af[mg], bf);
                    mma16(acc[mg * NT + 2 * np + 1], af[mg], bf + 2);
                }
            }
        }
        __syncthreads();
    }
}

__global__ void __launch_bounds__(NTHR, 1)
fusedh(const float* __restrict__ edge,
       const float* __restrict__ b_t1v,
       const float* __restrict__ ln_g,
       const float* __restrict__ ln_b,
       float* __restrict__ out) {
    extern __shared__ __align__(16) char smc[];
    const uint32_t sb = smem_u32(smc);
    const int tid = threadIdx.x, lane = tid & 31, w = tid >> 5;
    const int rowg = w & 1, colg = w >> 1;      // 2 x 8 warp grid
    const int m0 = rowg << 5;                   // warp's 32-row base
    const int bidx = blockIdx.x;
    const int i = bidx >> 3, j0 = (bidx & 7) << 6;

    // ---- edge -> E (fp16, [64][136]) ----
    {
        const float4* ep = (const float4*)(edge + (size_t)(i * NSEQ + j0) * 128);
#pragma unroll
        for (int s = 0; s < 4; s++) {
            int u = tid + (s << 9);
            int r = u >> 5, c4 = u & 31;
            float4 v = ep[(r << 5) + c4];
            union { uint2 u2; __half2 h[2]; } pk;
            pk.h[0] = __floats2half2_rn(v.x, v.y);
            pk.h[1] = __floats2half2_rn(v.z, v.w);
            *(uint2*)(smc + E_OFF + (uint32_t)((r * 136 + (c4 << 2)) << 1)) = pk.u2;
        }
    }
    __syncthreads();

    const int rbase = m0 + (lane >> 2);

    // ================= phase A-1: D0 = E @ W0top  (K=128, N=384) ============
    {
        float acc[12][4];
#pragma unroll
        for (int x = 0; x < 12; x++)
#pragma unroll
            for (int y = 0; y < 4; y++) acc[x][y] = 0.f;
        run_gemm<6, 32, 4>(g_w0h, 128, HID, sb + E_OFF + m0 * 272, 136,
                           colg * 48, sb + B0_OFF, sb + B1_OFF, acc, tid, lane);
        // epilogue: t0 = relu(D0 + P0i[i] + P0j[j0+m])
        const float* p0i = g_p0i + (size_t)i * HID;
        const float* p0j = g_p0j + (size_t)j0 * HID;
#pragma unroll
        for (int mg = 0; mg < 2; mg++) {
            const int r0 = rbase + (mg << 4);
#pragma unroll
            for (int ng = 0; ng < 6; ng++) {
                const int cb = colg * 48 + (ng << 3) + ((lane & 3) << 1);
                float2 bi  = *(const float2*)(p0i + cb);
                float2 bj0 = *(const float2*)(p0j + (size_t)r0 * HID + cb);
                float2 bj1 = *(const float2*)(p0j + (size_t)(r0 + 8) * HID + cb);
                const float* a = acc[mg * 6 + ng];
                *(__half2*)(smc + T0_OFF + (uint32_t)((r0 * 392 + cb) << 1)) =
                    __floats2half2_rn(fmaxf(a[0] + bi.x + bj0.x, 0.f),
                                      fmaxf(a[1] + bi.y + bj0.y, 0.f));
                *(__half2*)(smc + T0_OFF + (uint32_t)(((r0 + 8) * 392 + cb) << 1)) =
                    __floats2half2_rn(fmaxf(a[2] + bi.x + bj1.x, 0.f),
                                      fmaxf(a[3] + bi.y + bj1.y, 0.f));
            }
        }
    }

    // ================= phase A-2: R = E @ Wf_top  (K=128, N=128) ============
    {
        float acc[4][4];
#pragma unroll
        for (int x = 0; x < 4; x++)
#pragma unroll
            for (int y = 0; y < 4; y++) acc[x][y] = 0.f;
        run_gemm<2, 32, 4>(g_wrh, 128, EOUT, sb + E_OFF + m0 * 272, 136,
                           colg * 16, sb + B0_OFF, sb + B1_OFF, acc, tid, lane);
#pragma unroll
        for (int mg = 0; mg < 2; mg++) {
            const int r0 = rbase + (mg << 4);
#pragma unroll
            for (int ng = 0; ng < 2; ng++) {
                const int cb = colg * 16 + (ng << 3) + ((lane & 3) << 1);
                const float* a = acc[mg * 2 + ng];
                *(__half2*)(smc + R_OFF + (uint32_t)((r0 * 136 + cb) << 1)) =
                    __floats2half2_rn(a[0], a[1]);
                *(__half2*)(smc + R_OFF + (uint32_t)(((r0 + 8) * 136 + cb) << 1)) =
                    __floats2half2_rn(a[2], a[3]);
            }
        }
    }

    // ================= layer 1: rs = relu(t0 @ W1 + b1)  (K=384, N=384) =====
    {
        float acc[12][4];
#pragma unroll
        for (int x = 0; x < 12; x++)
#pragma unroll
            for (int y = 0; y < 4; y++) acc[x][y] = 0.f;
        run_gemm<6, 48, 8>(g_w1h, HID, HID, sb + T0_OFF + m0 * 784, 392,
                           colg * 48, sb + B0_OFF, sb + B1_OFF, acc, tid, lane);
#pragma unroll
        for (int mg = 0; mg < 2; mg++) {
            const int r0 = rbase + (mg << 4);
#pragma unroll
            for (int ng = 0; ng < 6; ng++) {
                const int cb = colg * 48 + (ng << 3) + ((lane & 3) << 1);
                float2 bb = *(const float2*)(b_t1v + cb);
                const float* a = acc[mg * 6 + ng];
                *(__half2*)(smc + RS_OFF + (uint32_t)((r0 * 392 + cb) << 1)) =
                    __floats2half2_rn(fmaxf(a[0] + bb.x, 0.f),
                                      fmaxf(a[1] + bb.y, 0.f));
                *(__half2*)(smc + RS_OFF + (uint32_t)(((r0 + 8) * 392 + cb) << 1)) =
                    __floats2half2_rn(fmaxf(a[2] + bb.x, 0.f),
                                      fmaxf(a[3] + bb.y, 0.f));
            }
        }
    }

    // ================= final: o = rs @ Wf + R + Pfi + Pfj  (K=384, N=128) ===
    {
        float acc[4][4];
#pragma unroll
        for (int mg = 0; mg < 2; mg++) {
            const int r0 = rbase + (mg << 4);
#pragma unroll
            for (int ng = 0; ng < 2; ng++) {
                const int cb = colg * 16 + (ng << 3) + ((lane & 3) << 1);
                float2 f0 = __half22float2(
                    *(__half2*)(smc + R_OFF + (uint32_t)((r0 * 136 + cb) << 1)));
                float2 f1 = __half22float2(
                    *(__half2*)(smc + R_OFF + (uint32_t)(((r0 + 8) * 136 + cb) << 1)));
                acc[mg * 2 + ng][0] = f0.x; acc[mg * 2 + ng][1] = f0.y;
                acc[mg * 2 + ng][2] = f1.x; acc[mg * 2 + ng][3] = f1.y;
            }
        }
        run_gemm<2, 48, 8>(g_wfh, HID, EOUT, sb + RS_OFF + m0 * 784, 392,
                           colg * 16, sb + B0_OFF, sb + B1_OFF, acc, tid, lane);
        // epilogue -> o_buf (fp32, overlays E+R — R fully consumed above)
        const float* pfi = g_pfi + (size_t)i * EOUT;
        const float* pfj = g_pfj + (size_t)j0 * EOUT;
        float* ob = (float*)(smc + O_OFF);
#pragma unroll
        for (int mg = 0; mg < 2; mg++) {
            const int r0 = rbase + (mg << 4);
#pragma unroll
            for (int ng = 0; ng < 2; ng++) {
                const int cb = colg * 16 + (ng << 3) + ((lane & 3) << 1);
                float2 fi  = *(const float2*)(pfi + cb);
                float2 fj0 = *(const float2*)(pfj + (size_t)r0 * EOUT + cb);
                float2 fj1 = *(const float2*)(pfj + (size_t)(r0 + 8) * EOUT + cb);
                const float* a = acc[mg * 2 + ng];
                float2 v0 = { a[0] + fi.x + fj0.x, a[1] + fi.y + fj0.y };
                float2 v1 = { a[2] + fi.x + fj1.x, a[3] + fi.y + fj1.y };
                *(float2*)(ob + r0 * 132 + cb)       = v0;
                *(float2*)(ob + (r0 + 8) * 132 + cb) = v1;
            }
        }
    }
    __syncthreads();

    // ---- LayerNorm over 128 + store: warp w owns rows w*4 .. w*4+3 ----
    {
        const float* ob = (const float*)(smc + O_OFF);
        const float g0 = ln_g[lane],      b0 = ln_b[lane];
        const float g1 = ln_g[lane + 32], b1 = ln_b[lane + 32];
        const float g2 = ln_g[lane + 64], b2 = ln_b[lane + 64];
        const float g3 = ln_g[lane + 96], b3 = ln_b[lane + 96];
#pragma unroll
        for (int rr = 0; rr < 4; rr++) {
            const int m = w * 4 + rr;
            const float* row = ob + m * 132;
            float v0 = row[lane], v1 = row[lane + 32];
            float v2 = row[lane + 64], v3 = row[lane + 96];
            float s = v0 + v1 + v2 + v3;
#pragma unroll
            for (int off = 16; off; off >>= 1)
                s += __shfl_xor_sync(0xffffffffu, s, off);
            const float mu = s * (1.0f / 128.0f);
            float d0 = v0 - mu, d1 = v1 - mu, d2 = v2 - mu, d3 = v3 - mu;
            float q = d0 * d0 + d1 * d1 + d2 * d2 + d3 * d3;
#pragma unroll
            for (int off = 16; off; off >>= 1)
                q += __shfl_xor_sync(0xffffffffu, q, off);
            const float rstd = rsqrtf(q * (1.0f / 128.0f) + 1e-5f);
            float* op = out + (size_t)(i * NSEQ + j0 + m) * EOUT;
            op[lane]      = d0 * rstd * g0 + b0;
            op[lane + 32] = d1 * rstd * g1 + b1;
            op[lane + 64] = d2 * rstd * g2 + b2;
            op[lane + 96] = d3 * rstd * g3 + b3;
        }
    }
}

// ---------------------------------------------------------------------------
extern "C" void kernel_launch(void* const* d_in, const int* in_sizes, int n_in,
                              void* d_out, int out_size) {
    const float* node   = (const float*)d_in[0];
    const float* edge   = (const float*)d_in[1];
    const float* w_init = (const float*)d_in[2];
    const float* b_init = (const float*)d_in[3];
    const float* w_t0   = (const float*)d_in[4];
    const float* b_t0   = (const float*)d_in[5];
    const float* w_t1   = (const float*)d_in[6];
    const float* b_t1   = (const float*)d_in[7];
    const float* w_fin  = (const float*)d_in[8];
    const float* b_fin  = (const float*)d_in[9];
    const float* ln_g   = (const float*)d_in[10];
    const float* ln_b   = (const float*)d_in[11];
    float* out = (float*)d_out;
    (void)in_sizes; (void)n_in; (void)out_size;

    cudaFuncSetAttribute(fusedh,
                         cudaFuncAttributeMaxDynamicSharedMemorySize, SMEMSZ);

    packh_kernel<<<256, 256>>>(w_t0, w_t1, w_fin);
    nb_kernel<<<NSEQ, 128>>>(node, w_init, b_init);
    pre_kernel<<<NSEQ, HID>>>(w_t0, b_t0, w_fin, b_fin);
    fusedh<<<4096, NTHR, SMEMSZ>>>(edge, b_t1, ln_g, ln_b, out);
}

// round 11
// speedup vs baseline: 1.5978x; 1.5978x over previous
#include <cuda_runtime.h>
#include <cuda_fp16.h>
#include <cstdint>
#include <cstddef>

#define NSEQ 512
#define HID  384
#define EOUT 128

// ---------------------------------------------------------------------------
// device-global scratch (no allocations allowed)
// ---------------------------------------------------------------------------
__device__ float g_nb [NSEQ * 128];
__device__ __align__(16) float g_p0i[NSEQ * HID];
__device__ __align__(16) float g_p0j[NSEQ * HID];
__device__ __align__(16) float g_pfi[NSEQ * EOUT];
__device__ __align__(16) float g_pfj[NSEQ * EOUT];

// fragment-packed fp16 weights for direct-from-L2 B operands.
// layout: uint32 idx = ((kc*NBTOT + nb)*32 + lane)*4 + r
//   r0 = {W[k0][n],W[k0+1][n]}, r1 = {k0+8}, r2 = {k0+16}, r3 = {k0+24}
//   where k0 = kc*32 + 2*(lane&3)  [r>>1 selects +16, r&1 selects +8]
//   and   n  = nb*8 + (lane>>2)
__device__ __align__(16) uint32_t g_pw0[4  * 48 * 128];  // W0top  K=128 N=384
__device__ __align__(16) uint32_t g_pwr[4  * 16 * 128];  // Wf_top K=128 N=128
__device__ __align__(16) uint32_t g_pw1[12 * 48 * 128];  // W1     K=384 N=384
__device__ __align__(16) uint32_t g_pwf[12 * 16 * 128];  // Wf     K=384 N=128

// ---------------------------------------------------------------------------
// helpers (baseline PTX only: mma.sync / ldmatrix)
// ---------------------------------------------------------------------------
__device__ __forceinline__ uint32_t smem_u32(const void* p) {
    uint32_t a;
    asm("{ .reg .u64 t; cvta.to.shared.u64 t, %1; cvt.u32.u64 %0, t; }"
        : "=r"(a) : "l"(p));
    return a;
}
__device__ __forceinline__ void ldmx4(uint32_t* r, uint32_t a) {
    asm volatile("ldmatrix.sync.aligned.m8n8.x4.shared.b16 {%0,%1,%2,%3}, [%4];"
                 : "=r"(r[0]), "=r"(r[1]), "=r"(r[2]), "=r"(r[3]) : "r"(a));
}
__device__ __forceinline__ void mma16(float* c, const uint32_t* a, const uint32_t* b) {
    asm volatile("mma.sync.aligned.m16n8k16.row.col.f32.f16.f16.f32 "
                 "{%0,%1,%2,%3},{%4,%5,%6,%7},{%8,%9},{%0,%1,%2,%3};"
                 : "+f"(c[0]), "+f"(c[1]), "+f"(c[2]), "+f"(c[3])
                 : "r"(a[0]), "r"(a[1]), "r"(a[2]), "r"(a[3]),
                   "r"(b[0]), "r"(b[1]));
}

// ---------------------------------------------------------------------------
// prep kernels
// ---------------------------------------------------------------------------
__global__ void nb_kernel(const float* __restrict__ node,
                          const float* __restrict__ w_init,
                          const float* __restrict__ b_init) {
    __shared__ float xs[256];
    int i = blockIdx.x, t = threadIdx.x;   // 128 threads
    xs[t]       = node[i * 256 + t];
    xs[t + 128] = node[i * 256 + 128 + t];
    __syncthreads();
    float acc = b_init[t];
#pragma unroll 8
    for (int k = 0; k < 256; k++) acc += xs[k] * w_init[k * 128 + t];
    g_nb[i * 128 + t] = acc;
}

__global__ void pre_kernel(const float* __restrict__ w_t0,
                           const float* __restrict__ b_t0,
                           const float* __restrict__ w_fin,
                           const float* __restrict__ b_fin) {
    __shared__ float nbs[128];
    int i = blockIdx.x, t = threadIdx.x;   // 384 threads
    if (t < 128) nbs[t] = g_nb[i * 128 + t];
    __syncthreads();
    float a0 = b_t0[t], a1 = 0.f;
#pragma unroll 8
    for (int k = 0; k < 128; k++) {
        float v = nbs[k];
        a0 += v * w_t0[(128 + k) * HID + t];
        a1 += v * w_t0[(256 + k) * HID + t];
    }
    g_p0i[i * HID + t] = a0;
    g_p0j[i * HID + t] = a1;
    if (t < 128) {
        float f0 = b_fin[t], f1 = 0.f;
#pragma unroll 8
        for (int k = 0; k < 128; k++) {
            float v = nbs[k];
            f0 += v * w_fin[(128 + k) * EOUT + t];
            f1 += v * w_fin[(256 + k) * EOUT + t];
        }
        g_pfi[i * EOUT + t] = f0;
        g_pfj[i * EOUT + t] = f1;
    }
}

// pack weights into per-lane mma B-fragment layout (see g_pw0 comment)
__device__ __forceinline__ uint32_t pack_elem(const float* W, int N,
                                              int x, int nbTot) {
    int r = x & 3, lane = (x >> 2) & 31, rest = x >> 7;
    int nb = rest % nbTot, kc = rest / nbTot;
    int k = kc * 32 + ((r >> 1) << 4) + ((r & 1) << 3) + ((lane & 3) << 1);
    int n = nb * 8 + (lane >> 2);
    __half2 h = __floats2half2_rn(W[k * N + n], W[(k + 1) * N + n]);
    return *(uint32_t*)&h;
}

__global__ void packh_kernel(const float* __restrict__ w_t0,
                             const float* __restrict__ w_t1,
                             const float* __restrict__ w_fin) {
    const int T0 = 4 * 48 * 128, T1 = 4 * 16 * 128;
    const int T2 = 12 * 48 * 128, T3 = 12 * 16 * 128;
    for (int x = blockIdx.x * blockDim.x + threadIdx.x; x < T0 + T1 + T2 + T3;
         x += gridDim.x * blockDim.x) {
        if (x < T0)                 g_pw0[x]           = pack_elem(w_t0,  HID,  x,           48);
        else if (x < T0 + T1)       g_pwr[x - T0]      = pack_elem(w_fin, EOUT, x - T0,      16);
        else if (x < T0 + T1 + T2)  g_pw1[x - T0 - T1] = pack_elem(w_t1,  HID,  x - T0 - T1, 48);
        else                        g_pwf[x - T0 - T1 - T2] =
                                        pack_elem(w_fin, EOUT, x - T0 - T1 - T2, 16);
    }
}

// ---------------------------------------------------------------------------
// fused kernel: M=64 rows/CTA, 512 thr = 16 warps, warp grid 1 x 16 (colg).
// Each warp: full 64 rows (mg=4) x (NB*8) cols. B direct from L2 (packed).
// SMEM (bytes):
//   t0 [64][392]h @ 0        (50176)
//   rs [64][392]h @ 50176    (50176)
//   E  [64][136]h @ 100352   (17408)  } o_buf [64][132]f @100352 (33792)
//   R  [64][136]h @ 117760   (17408)  }   overlays E+R after both dead
// total 135168
// ---------------------------------------------------------------------------
#define T0_OFF 0
#define RS_OFF 50176
#define E_OFF  100352
#define R_OFF  117760
#define O_OFF  100352
#define SMEMSZ 135168
#define NTHR   512

// gBt: per-thread B pointer (uint4, already offset by warp nb base + lane).
// kstride = nbTot*32 uint4 per kc chunk.
template <int NB, int KC>
__device__ __forceinline__ void gemm_g(const uint4* __restrict__ gBt, int kstride,
                                       uint32_t aBase, int lda,
                                       float (*acc)[4], int lane) {
    uint4 bb[3][NB];
#pragma unroll
    for (int p = 0; p < 2; p++)
#pragma unroll
        for (int nb = 0; nb < NB; nb++)
            bb[p][nb] = gBt[p * kstride + nb * 32];
    const uint32_t aro = lane & 15;
    const uint32_t ako = (lane >> 4) << 3;
#pragma unroll
    for (int kc = 0; kc < KC; kc++) {
        if (kc + 2 < KC) {
#pragma unroll
            for (int nb = 0; nb < NB; nb++)
                bb[(kc + 2) % 3][nb] = gBt[(kc + 2) * kstride + nb * 32];
        }
        const uint4* bc = bb[kc % 3];
        uint32_t af[4][4];
        // kk = 0
#pragma unroll
        for (int mg = 0; mg < 4; mg++)
            ldmx4(af[mg], aBase + 2u * ((mg * 16 + aro) * lda + kc * 32 + ako));
#pragma unroll
        for (int nb = 0; nb < NB; nb++) {
            uint32_t bf[2] = { bc[nb].x, bc[nb].y };
#pragma unroll
            for (int mg = 0; mg < 4; mg++)
                mma16(acc[mg * NB + nb], af[mg], bf);
        }
        // kk = 16
#pragma unroll
        for (int mg = 0; mg < 4; mg++)
            ldmx4(af[mg], aBase + 2u * ((mg * 16 + aro) * lda + kc * 32 + 16 + ako));
#pragma unroll
        for (int nb = 0; nb < NB; nb++) {
            uint32_t bf[2] = { bc[nb].z, bc[nb].w };
#pragma unroll
            for (int mg = 0; mg < 4; mg++)
                mma16(acc[mg * NB + nb], af[mg], bf);
        }
    }
}

__global__ void __launch_bounds__(NTHR, 1)
fusedh(const float* __restrict__ edge,
       const float* __restrict__ b_t1v,
       const float* __restrict__ ln_g,
       const float* __restrict__ ln_b,
       float* __restrict__ out) {
    extern __shared__ __align__(16) char smc[];
    const uint32_t sb = smem_u32(smc);
    const int tid = threadIdx.x, lane = tid & 31, w = tid >> 5;
    const int colg = w;                          // 1 x 16 warp grid
    const int bidx = blockIdx.x;
    const int i = bidx >> 3, j0 = (bidx & 7) << 6;

    // ---- edge -> E (fp16, [64][136]) ----
    {
        const float4* ep = (const float4*)(edge + (size_t)(i * NSEQ + j0) * 128);
#pragma unroll
        for (int s = 0; s < 4; s++) {
            int u = tid + (s << 9);
            int r = u >> 5, c4 = u & 31;
            float4 v = ep[(r << 5) + c4];
            union { uint2 u2; __half2 h[2]; } pk;
            pk.h[0] = __floats2half2_rn(v.x, v.y);
            pk.h[1] = __floats2half2_rn(v.z, v.w);
            *(uint2*)(smc + E_OFF + (uint32_t)((r * 136 + (c4 << 2)) << 1)) = pk.u2;
        }
    }
    __syncthreads();

    const int rq = lane >> 2;                 // acc row within m16 group
    const int c2 = (lane & 3) << 1;           // acc col pair within n8

    // ================= phase A-1: D0 = E @ W0top  (K=128, N=384) ============
    {
        float acc[12][4];
#pragma unroll
        for (int x = 0; x < 12; x++)
#pragma unroll
            for (int y = 0; y < 4; y++) acc[x][y] = 0.f;
        const uint4* gBt = (const uint4*)g_pw0 + (colg * 3) * 32 + lane;
        gemm_g<3, 4>(gBt, 48 * 32, sb + E_OFF, 136, acc, lane);
        // epilogue: t0 = relu(D0 + P0i[i] + P0j[j0+m])
        const float* p0i = g_p0i + (size_t)i * HID;
        const float* p0j = g_p0j + (size_t)j0 * HID;
#pragma unroll
        for (int mg = 0; mg < 4; mg++) {
            const int r0 = mg * 16 + rq;
#pragma unroll
            for (int ng = 0; ng < 3; ng++) {
                const int cb = colg * 24 + (ng << 3) + c2;
                float2 bi  = *(const float2*)(p0i + cb);
                float2 bj0 = *(const float2*)(p0j + (size_t)r0 * HID + cb);
                float2 bj1 = *(const float2*)(p0j + (size_t)(r0 + 8) * HID + cb);
                const float* a = acc[mg * 3 + ng];
                *(__half2*)(smc + T0_OFF + (uint32_t)((r0 * 392 + cb) << 1)) =
                    __floats2half2_rn(fmaxf(a[0] + bi.x + bj0.x, 0.f),
                                      fmaxf(a[1] + bi.y + bj0.y, 0.f));
                *(__half2*)(smc + T0_OFF + (uint32_t)(((r0 + 8) * 392 + cb) << 1)) =
                    __floats2half2_rn(fmaxf(a[2] + bi.x + bj1.x, 0.f),
                                      fmaxf(a[3] + bi.y + bj1.y, 0.f));
            }
        }
    }

    // ================= phase A-2: R = E @ Wf_top  (K=128, N=128) ============
    {
        float acc[4][4];
#pragma unroll
        for (int x = 0; x < 4; x++)
#pragma unroll
            for (int y = 0; y < 4; y++) acc[x][y] = 0.f;
        const uint4* gBt = (const uint4*)g_pwr + colg * 32 + lane;
        gemm_g<1, 4>(gBt, 16 * 32, sb + E_OFF, 136, acc, lane);
#pragma unroll
        for (int mg = 0; mg < 4; mg++) {
            const int r0 = mg * 16 + rq;
            const int cb = colg * 8 + c2;
            const float* a = acc[mg];
            *(__half2*)(smc + R_OFF + (uint32_t)((r0 * 136 + cb) << 1)) =
                __floats2half2_rn(a[0], a[1]);
            *(__half2*)(smc + R_OFF + (uint32_t)(((r0 + 8) * 136 + cb) << 1)) =
                __floats2half2_rn(a[2], a[3]);
        }
    }
    __syncthreads();   // t0 fully written & visible

    // ================= layer 1: rs = relu(t0 @ W1 + b1)  (K=384, N=384) =====
    {
        float acc[12][4];
#pragma unroll
        for (int x = 0; x < 12; x++)
#pragma unroll
            for (int y = 0; y < 4; y++) acc[x][y] = 0.f;
        const uint4* gBt = (const uint4*)g_pw1 + (colg * 3) * 32 + lane;
        gemm_g<3, 12>(gBt, 48 * 32, sb + T0_OFF, 392, acc, lane);
#pragma unroll
        for (int mg = 0; mg < 4; mg++) {
            const int r0 = mg * 16 + rq;
#pragma unroll
            for (int ng = 0; ng < 3; ng++) {
                const int cb = colg * 24 + (ng << 3) + c2;
                float2 bb = *(const float2*)(b_t1v + cb);
                const float* a = acc[mg * 3 + ng];
                *(__half2*)(smc + RS_OFF + (uint32_t)((r0 * 392 + cb) << 1)) =
                    __floats2half2_rn(fmaxf(a[0] + bb.x, 0.f),
                                      fmaxf(a[1] + bb.y, 0.f));
                *(__half2*)(smc + RS_OFF + (uint32_t)(((r0 + 8) * 392 + cb) << 1)) =
                    __floats2half2_rn(fmaxf(a[2] + bb.x, 0.f),
                                      fmaxf(a[3] + bb.y, 0.f));
            }
        }
    }
    __syncthreads();   // rs fully written & visible

    // ================= final: o = rs @ Wf + R + Pfi + Pfj  (K=384, N=128) ===
    {
        float acc[4][4];
        // init accumulator from R (same warp tile that wrote it)
#pragma unroll
        for (int mg = 0; mg < 4; mg++) {
            const int r0 = mg * 16 + rq;
            const int cb = colg * 8 + c2;
            float2 f0 = __half22float2(
                *(__half2*)(smc + R_OFF + (uint32_t)((r0 * 136 + cb) << 1)));
            float2 f1 = __half22float2(
                *(__half2*)(smc + R_OFF + (uint32_t)(((r0 + 8) * 136 + cb) << 1)));
            acc[mg][0] = f0.x; acc[mg][1] = f0.y;
            acc[mg][2] = f1.x; acc[mg][3] = f1.y;
        }
        __syncthreads();   // all R reads done before o_buf overlays those bytes
        const uint4* gBt = (const uint4*)g_pwf + colg * 32 + lane;
        gemm_g<1, 12>(gBt, 16 * 32, sb + RS_OFF, 392, acc, lane);
        // epilogue -> o_buf (fp32, overlays E+R)
        const float* pfi = g_pfi + (size_t)i * EOUT;
        const float* pfj = g_pfj + (size_t)j0 * EOUT;
        float* ob = (float*)(smc + O_OFF);
#pragma unroll
        for (int mg = 0; mg < 4; mg++) {
            const int r0 = mg * 16 + rq;
            const int cb = colg * 8 + c2;
            float2 fi  = *(const float2*)(pfi + cb);
            float2 fj0 = *(const float2*)(pfj + (size_t)r0 * EOUT + cb);
            float2 fj1 = *(const float2*)(pfj + (size_t)(r0 + 8) * EOUT + cb);
            const float* a = acc[mg];
            float2 v0 = { a[0] + fi.x + fj0.x, a[1] + fi.y + fj0.y };
            float2 v1 = { a[2] + fi.x + fj1.x, a[3] + fi.y + fj1.y };
            *(float2*)(ob + r0 * 132 + cb)       = v0;
            *(float2*)(ob + (r0 + 8) * 132 + cb) = v1;
        }
    }
    __syncthreads();

    // ---- LayerNorm over 128 + store: warp w owns rows w*4 .. w*4+3 ----
    {
        const float* ob = (const float*)(smc + O_OFF);
        const float g0 = ln_g[lane],      b0 = ln_b[lane];
        const float g1 = ln_g[lane + 32], b1 = ln_b[lane + 32];
        const float g2 = ln_g[lane + 64], b2 = ln_b[lane + 64];
        const float g3 = ln_g[lane + 96], b3 = ln_b[lane + 96];
#pragma unroll
        for (int rr = 0; rr < 4; rr++) {
            const int m = w * 4 + rr;
            const float* row = ob + m * 132;
            float v0 = row[lane], v1 = row[lane + 32];
            float v2 = row[lane + 64], v3 = row[lane + 96];
            float s = v0 + v1 + v2 + v3;
#pragma unroll
            for (int off = 16; off; off >>= 1)
                s += __shfl_xor_sync(0xffffffffu, s, off);
            const float mu = s * (1.0f / 128.0f);
            float d0 = v0 - mu, d1 = v1 - mu, d2 = v2 - mu, d3 = v3 - mu;
            float q = d0 * d0 + d1 * d1 + d2 * d2 + d3 * d3;
#pragma unroll
            for (int off = 16; off; off >>= 1)
                q += __shfl_xor_sync(0xffffffffu, q, off);
            const float rstd = rsqrtf(q * (1.0f / 128.0f) + 1e-5f);
            float* op = out + (size_t)(i * NSEQ + j0 + m) * EOUT;
            op[lane]      = d0 * rstd * g0 + b0;
            op[lane + 32] = d1 * rstd * g1 + b1;
            op[lane + 64] = d2 * rstd * g2 + b2;
            op[lane + 96] = d3 * rstd * g3 + b3;
        }
    }
}

// ---------------------------------------------------------------------------
extern "C" void kernel_launch(void* const* d_in, const int* in_sizes, int n_in,
                              void* d_out, int out_size) {
    const float* node   = (const float*)d_in[0];
    const float* edge   = (const float*)d_in[1];
    const float* w_init = (const float*)d_in[2];
    const float* b_init = (const float*)d_in[3];
    const float* w_t0   = (const float*)d_in[4];
    const float* b_t0   = (const float*)d_in[5];
    const float* w_t1   = (const float*)d_in[6];
    const float* b_t1   = (const float*)d_in[7];
    const float* w_fin  = (const float*)d_in[8];
    const float* b_fin  = (const float*)d_in[9];
    const float* ln_g   = (const float*)d_in[10];
    const float* ln_b   = (const float*)d_in[11];
    float* out = (float*)d_out;
    (void)in_sizes; (void)n_in; (void)out_size;

    cudaFuncSetAttribute(fusedh,
                         cudaFuncAttributeMaxDynamicSharedMemorySize, SMEMSZ);

    packh_kernel<<<256, 256>>>(w_t0, w_t1, w_fin);
    nb_kernel<<<NSEQ, 128>>>(node, w_init, b_init);
    pre_kernel<<<NSEQ, HID>>>(w_t0, b_t0, w_fin, b_fin);
    fusedh<<<4096, NTHR, SMEMSZ>>>(edge, b_t1, ln_g, ln_b, out);
}

// round 14
// speedup vs baseline: 1.7405x; 1.0893x over previous
#include <cuda_runtime.h>
#include <cuda_fp16.h>
#include <cstdint>
#include <cstddef>

#define NSEQ 512
#define HID  384
#define EOUT 128

// ---------------------------------------------------------------------------
// device-global scratch (no allocations allowed)
// ---------------------------------------------------------------------------
__device__ float g_nb [NSEQ * 128];
__device__ __align__(16) float g_p0i[NSEQ * HID];
__device__ __align__(16) float g_p0j[NSEQ * HID];
__device__ __align__(16) float g_pfi[NSEQ * EOUT];
__device__ __align__(16) float g_pfj[NSEQ * EOUT];

// fragment-packed fp16 weights for direct-from-L2 B operands.
// layout: uint32 idx = ((kc*NBTOT + nb)*32 + lane)*4 + r
//   r0 = {W[k0][n],W[k0+1][n]}, r1 = {k0+8}, r2 = {k0+16}, r3 = {k0+24}
//   where k0 = kc*32 + 2*(lane&3)  [r>>1 selects +16, r&1 selects +8]
//   and   n  = nb*8 + (lane>>2)
__device__ __align__(16) uint32_t g_pw0[4  * 48 * 128];  // W0top  K=128 N=384
__device__ __align__(16) uint32_t g_pwr[4  * 16 * 128];  // Wf_top K=128 N=128
__device__ __align__(16) uint32_t g_pw1[12 * 48 * 128];  // W1     K=384 N=384
__device__ __align__(16) uint32_t g_pwf[12 * 16 * 128];  // Wf     K=384 N=128

// ---------------------------------------------------------------------------
// helpers (baseline PTX only: mma.sync / ldmatrix)
// ---------------------------------------------------------------------------
__device__ __forceinline__ uint32_t smem_u32(const void* p) {
    uint32_t a;
    asm("{ .reg .u64 t; cvta.to.shared.u64 t, %1; cvt.u32.u64 %0, t; }"
        : "=r"(a) : "l"(p));
    return a;
}
__device__ __forceinline__ void ldmx4(uint32_t* r, uint32_t a) {
    asm volatile("ldmatrix.sync.aligned.m8n8.x4.shared.b16 {%0,%1,%2,%3}, [%4];"
                 : "=r"(r[0]), "=r"(r[1]), "=r"(r[2]), "=r"(r[3]) : "r"(a));
}
__device__ __forceinline__ void mma16(float* c, const uint32_t* a, const uint32_t* b) {
    asm volatile("mma.sync.aligned.m16n8k16.row.col.f32.f16.f16.f32 "
                 "{%0,%1,%2,%3},{%4,%5,%6,%7},{%8,%9},{%0,%1,%2,%3};"
                 : "+f"(c[0]), "+f"(c[1]), "+f"(c[2]), "+f"(c[3])
                 : "r"(a[0]), "r"(a[1]), "r"(a[2]), "r"(a[3]),
                   "r"(b[0]), "r"(b[1]));
}

// ---------------------------------------------------------------------------
// prep kernels
// ---------------------------------------------------------------------------
__global__ void nb_kernel(const float* __restrict__ node,
                          const float* __restrict__ w_init,
                          const float* __restrict__ b_init) {
    __shared__ float xs[256];
    int i = blockIdx.x, t = threadIdx.x;   // 128 threads
    xs[t]       = node[i * 256 + t];
    xs[t + 128] = node[i * 256 + 128 + t];
    __syncthreads();
    float acc = b_init[t];
#pragma unroll 8
    for (int k = 0; k < 256; k++) acc += xs[k] * w_init[k * 128 + t];
    g_nb[i * 128 + t] = acc;
}

__global__ void pre_kernel(const float* __restrict__ w_t0,
                           const float* __restrict__ b_t0,
                           const float* __restrict__ w_fin,
                           const float* __restrict__ b_fin) {
    __shared__ float nbs[128];
    int i = blockIdx.x, t = threadIdx.x;   // 384 threads
    if (t < 128) nbs[t] = g_nb[i * 128 + t];
    __syncthreads();
    float a0 = b_t0[t], a1 = 0.f;
#pragma unroll 8
    for (int k = 0; k < 128; k++) {
        float v = nbs[k];
        a0 += v * w_t0[(128 + k) * HID + t];
        a1 += v * w_t0[(256 + k) * HID + t];
    }
    g_p0i[i * HID + t] = a0;
    g_p0j[i * HID + t] = a1;
    if (t < 128) {
        float f0 = b_fin[t], f1 = 0.f;
#pragma unroll 8
        for (int k = 0; k < 128; k++) {
            float v = nbs[k];
            f0 += v * w_fin[(128 + k) * EOUT + t];
            f1 += v * w_fin[(256 + k) * EOUT + t];
        }
        g_pfi[i * EOUT + t] = f0;
        g_pfj[i * EOUT + t] = f1;
    }
}

// pack weights into per-lane mma B-fragment layout (see g_pw0 comment)
__device__ __forceinline__ uint32_t pack_elem(const float* W, int N,
                                              int x, int nbTot) {
    int r = x & 3, lane = (x >> 2) & 31, rest = x >> 7;
    int nb = rest % nbTot, kc = rest / nbTot;
    int k = kc * 32 + ((r >> 1) << 4) + ((r & 1) << 3) + ((lane & 3) << 1);
    int n = nb * 8 + (lane >> 2);
    __half2 h = __floats2half2_rn(W[k * N + n], W[(k + 1) * N + n]);
    return *(uint32_t*)&h;
}

__global__ void packh_kernel(const float* __restrict__ w_t0,
                             const float* __restrict__ w_t1,
                             const float* __restrict__ w_fin) {
    const int T0 = 4 * 48 * 128, T1 = 4 * 16 * 128;
    const int T2 = 12 * 48 * 128, T3 = 12 * 16 * 128;
    for (int x = blockIdx.x * blockDim.x + threadIdx.x; x < T0 + T1 + T2 + T3;
         x += gridDim.x * blockDim.x) {
        if (x < T0)                 g_pw0[x]           = pack_elem(w_t0,  HID,  x,           48);
        else if (x < T0 + T1)       g_pwr[x - T0]      = pack_elem(w_fin, EOUT, x - T0,      16);
        else if (x < T0 + T1 + T2)  g_pw1[x - T0 - T1] = pack_elem(w_t1,  HID,  x - T0 - T1, 48);
        else                        g_pwf[x - T0 - T1 - T2] =
                                        pack_elem(w_fin, EOUT, x - T0 - T1 - T2, 16);
    }
}

// ---------------------------------------------------------------------------
// fused kernel: M=64 rows/CTA, 512 thr = 16 warps, grid 2 rowg x 8 colg.
// Each warp: 32 rows (mg=2) x (NB*8) cols. B direct from L2 (packed).
// SMEM (bytes):
//   t0 [64][392]h @ 0        (50176)
//   rs [64][392]h @ 50176    (50176)
//   E  [64][136]h @ 100352   (17408)  } o_buf [64][132]f @100352 (33792)
//   R  [64][136]h @ 117760   (17408)  }   overlays E+R after both dead
// total 135168
// ---------------------------------------------------------------------------
#define T0_OFF 0
#define RS_OFF 50176
#define E_OFF  100352
#define R_OFF  117760
#define O_OFF  100352
#define SMEMSZ 135168
#define NTHR   512

// gBt: per-thread B pointer (uint4, already offset by warp nb base + lane).
// kstride = nbTot*32 uint4 per kc chunk. PD = prefetch ring depth.
template <int NB, int KC, int PD>
__device__ __forceinline__ void gemm_g(const uint4* __restrict__ gBt, int kstride,
                                       uint32_t aBase, int lda,
                                       float (*acc)[4], int lane) {
    uint4 bb[PD][NB];
#pragma unroll
    for (int p = 0; p < PD - 1; p++)
#pragma unroll
        for (int nb = 0; nb < NB; nb++)
            bb[p][nb] = gBt[p * kstride + nb * 32];
    const uint32_t aro = lane & 15;
    const uint32_t ako = (lane >> 4) << 3;
#pragma unroll
    for (int kc = 0; kc < KC; kc++) {
        if (kc + PD - 1 < KC) {
#pragma unroll
            for (int nb = 0; nb < NB; nb++)
                bb[(kc + PD - 1) % PD][nb] = gBt[(kc + PD - 1) * kstride + nb * 32];
        }
        const uint4* bc = bb[kc % PD];
        uint32_t af[2][4];
        // kk = 0
#pragma unroll
        for (int mg = 0; mg < 2; mg++)
            ldmx4(af[mg], aBase + 2u * ((mg * 16 + aro) * lda + kc * 32 + ako));
#pragma unroll
        for (int nb = 0; nb < NB; nb++) {
            uint32_t bf[2] = { bc[nb].x, bc[nb].y };
#pragma unroll
            for (int mg = 0; mg < 2; mg++)
                mma16(acc[mg * NB + nb], af[mg], bf);
        }
        // kk = 16
#pragma unroll
        for (int mg = 0; mg < 2; mg++)
            ldmx4(af[mg], aBase + 2u * ((mg * 16 + aro) * lda + kc * 32 + 16 + ako));
#pragma unroll
        for (int nb = 0; nb < NB; nb++) {
            uint32_t bf[2] = { bc[nb].z, bc[nb].w };
#pragma unroll
            for (int mg = 0; mg < 2; mg++)
                mma16(acc[mg * NB + nb], af[mg], bf);
        }
    }
}

__global__ void __launch_bounds__(NTHR, 1)
fusedh(const float* __restrict__ edge,
       const float* __restrict__ b_t1v,
       const float* __restrict__ ln_g,
       const float* __restrict__ ln_b,
       float* __restrict__ out) {
    extern __shared__ __align__(16) char smc[];
    const uint32_t sb = smem_u32(smc);
    const int tid = threadIdx.x, lane = tid & 31, w = tid >> 5;
    const int rowg = w & 1, colg = w >> 1;       // 2 x 8 warp grid
    const int m0 = rowg << 5;                    // warp's 32-row base
    const int bidx = blockIdx.x;
    const int i = bidx >> 3, j0 = (bidx & 7) << 6;

    // ---- edge -> E (fp16, [64][136]) ----
    {
        const float4* ep = (const float4*)(edge + (size_t)(i * NSEQ + j0) * 128);
#pragma unroll
        for (int s = 0; s < 4; s++) {
            int u = tid + (s << 9);
            int r = u >> 5, c4 = u & 31;
            float4 v = ep[(r << 5) + c4];
            union { uint2 u2; __half2 h[2]; } pk;
            pk.h[0] = __floats2half2_rn(v.x, v.y);
            pk.h[1] = __floats2half2_rn(v.z, v.w);
            *(uint2*)(smc + E_OFF + (uint32_t)((r * 136 + (c4 << 2)) << 1)) = pk.u2;
        }
    }
    __syncthreads();

    const int rq = lane >> 2;                 // acc row within m16 group
    const int c2 = (lane & 3) << 1;           // acc col pair within n8

    // ================= phase A-1: D0 = E @ W0top  (K=128, N=384) ============
    {
        float acc[12][4];
#pragma unroll
        for (int x = 0; x < 12; x++)
#pragma unroll
            for (int y = 0; y < 4; y++) acc[x][y] = 0.f;
        const uint4* gBt = (const uint4*)g_pw0 + (colg * 6) * 32 + lane;
        gemm_g<6, 4, 2>(gBt, 48 * 32, sb + E_OFF + m0 * 272, 136, acc, lane);
        // epilogue: t0 = relu(D0 + P0i[i] + P0j[j0+m])
        const float* p0i = g_p0i + (size_t)i * HID;
        const float* p0j = g_p0j + (size_t)j0 * HID;
#pragma unroll
        for (int mg = 0; mg < 2; mg++) {
            const int r0 = m0 + mg * 16 + rq;
#pragma unroll
            for (int ng = 0; ng < 6; ng++) {
                const int cb = colg * 48 + (ng << 3) + c2;
                float2 bi  = *(const float2*)(p0i + cb);
                float2 bj0 = *(const float2*)(p0j + (size_t)r0 * HID + cb);
                float2 bj1 = *(const float2*)(p0j + (size_t)(r0 + 8) * HID + cb);
                const float* a = acc[mg * 6 + ng];
                *(__half2*)(smc + T0_OFF + (uint32_t)((r0 * 392 + cb) << 1)) =
                    __floats2half2_rn(fmaxf(a[0] + bi.x + bj0.x, 0.f),
                                      fmaxf(a[1] + bi.y + bj0.y, 0.f));
                *(__half2*)(smc + T0_OFF + (uint32_t)(((r0 + 8) * 392 + cb) << 1)) =
                    __floats2half2_rn(fmaxf(a[2] + bi.x + bj1.x, 0.f),
                                      fmaxf(a[3] + bi.y + bj1.y, 0.f));
            }
        }
    }

    // ================= phase A-2: R = E @ Wf_top  (K=128, N=128) ============
    {
        float acc[4][4];
#pragma unroll
        for (int x = 0; x < 4; x++)
#pragma unroll
            for (int y = 0; y < 4; y++) acc[x][y] = 0.f;
        const uint4* gBt = (const uint4*)g_pwr + (colg * 2) * 32 + lane;
        gemm_g<2, 4, 3>(gBt, 16 * 32, sb + E_OFF + m0 * 272, 136, acc, lane);
#pragma unroll
        for (int mg = 0; mg < 2; mg++) {
            const int r0 = m0 + mg * 16 + rq;
#pragma unroll
            for (int ng = 0; ng < 2; ng++) {
                const int cb = colg * 16 + (ng << 3) + c2;
                const float* a = acc[mg * 2 + ng];
                *(__half2*)(smc + R_OFF + (uint32_t)((r0 * 136 + cb) << 1)) =
                    __floats2half2_rn(a[0], a[1]);
                *(__half2*)(smc + R_OFF + (uint32_t)(((r0 + 8) * 136 + cb) << 1)) =
                    __floats2half2_rn(a[2], a[3]);
            }
        }
    }
    __syncthreads();   // t0 fully written & visible

    // ================= layer 1: rs = relu(t0 @ W1 + b1)  (K=384, N=384) =====
    {
        float acc[12][4];
#pragma unroll
        for (int x = 0; x < 12; x++)
#pragma unroll
            for (int y = 0; y < 4; y++) acc[x][y] = 0.f;
        const uint4* gBt = (const uint4*)g_pw1 + (colg * 6) * 32 + lane;
        gemm_g<6, 12, 2>(gBt, 48 * 32, sb + T0_OFF + m0 * 784, 392, acc, lane);
#pragma unroll
        for (int mg = 0; mg < 2; mg++) {
            const int r0 = m0 + mg * 16 + rq;
#pragma unroll
            for (int ng = 0; ng < 6; ng++) {
                const int cb = colg * 48 + (ng << 3) + c2;
                float2 bb = *(const float2*)(b_t1v + cb);
                const float* a = acc[mg * 6 + ng];
                *(__half2*)(smc + RS_OFF + (uint32_t)((r0 * 392 + cb) << 1)) =
                    __floats2half2_rn(fmaxf(a[0] + bb.x, 0.f),
                                      fmaxf(a[1] + bb.y, 0.f));
                *(__half2*)(smc + RS_OFF + (uint32_t)(((r0 + 8) * 392 + cb) << 1)) =
                    __floats2half2_rn(fmaxf(a[2] + bb.x, 0.f),
                                      fmaxf(a[3] + bb.y, 0.f));
            }
        }
    }
    __syncthreads();   // rs fully written & visible

    // ================= final: o = rs @ Wf + R + Pfi + Pfj  (K=384, N=128) ===
    {
        float acc[4][4];
        // init accumulator from R (same warp tile that wrote it)
#pragma unroll
        for (int mg = 0; mg < 2; mg++) {
            const int r0 = m0 + mg * 16 + rq;
#pragma unroll
            for (int ng = 0; ng < 2; ng++) {
                const int cb = colg * 16 + (ng << 3) + c2;
                float2 f0 = __half22float2(
                    *(__half2*)(smc + R_OFF + (uint32_t)((r0 * 136 + cb) << 1)));
                float2 f1 = __half22float2(
                    *(__half2*)(smc + R_OFF + (uint32_t)(((r0 + 8) * 136 + cb) << 1)));
                acc[mg * 2 + ng][0] = f0.x; acc[mg * 2 + ng][1] = f0.y;
                acc[mg * 2 + ng][2] = f1.x; acc[mg * 2 + ng][3] = f1.y;
            }
        }
        __syncthreads();   // all R reads done before o_buf overlays those bytes
        const uint4* gBt = (const uint4*)g_pwf + (colg * 2) * 32 + lane;
        gemm_g<2, 12, 3>(gBt, 16 * 32, sb + RS_OFF + m0 * 784, 392, acc, lane);
        // epilogue -> o_buf (fp32, overlays E+R)
        const float* pfi = g_pfi + (size_t)i * EOUT;
        const float* pfj = g_pfj + (size_t)j0 * EOUT;
        float* ob = (float*)(smc + O_OFF);
#pragma unroll
        for (int mg = 0; mg < 2; mg++) {
            const int r0 = m0 + mg * 16 + rq;
#pragma unroll
            for (int ng = 0; ng < 2; ng++) {
                const int cb = colg * 16 + (ng << 3) + c2;
                float2 fi  = *(const float2*)(pfi + cb);
                float2 fj0 = *(const float2*)(pfj + (size_t)r0 * EOUT + cb);
                float2 fj1 = *(const float2*)(pfj + (size_t)(r0 + 8) * EOUT + cb);
                const float* a = acc[mg * 2 + ng];
                float2 v0 = { a[0] + fi.x + fj0.x, a[1] + fi.y + fj0.y };
                float2 v1 = { a[2] + fi.x + fj1.x, a[3] + fi.y + fj1.y };
                *(float2*)(ob + r0 * 132 + cb)       = v0;
                *(float2*)(ob + (r0 + 8) * 132 + cb) = v1;
            }
        }
    }
    __syncthreads();

    // ---- LayerNorm over 128 + store: warp w owns rows w*4 .. w*4+3 ----
    {
        const float* ob = (const float*)(smc + O_OFF);
        const float g0 = ln_g[lane],      b0 = ln_b[lane];
        const float g1 = ln_g[lane + 32], b1 = ln_b[lane + 32];
        const float g2 = ln_g[lane + 64], b2 = ln_b[lane + 64];
        const float g3 = ln_g[lane + 96], b3 = ln_b[lane + 96];
#pragma unroll
        for (int rr = 0; rr < 4; rr++) {
            const int m = w * 4 + rr;
            const float* row = ob + m * 132;
            float v0 = row[lane], v1 = row[lane + 32];
            float v2 = row[lane + 64], v3 = row[lane + 96];
            float s = v0 + v1 + v2 + v3;
#pragma unroll
            for (int off = 16; off; off >>= 1)
                s += __shfl_xor_sync(0xffffffffu, s, off);
            const float mu = s * (1.0f / 128.0f);
            float d0 = v0 - mu, d1 = v1 - mu, d2 = v2 - mu, d3 = v3 - mu;
            float q = d0 * d0 + d1 * d1 + d2 * d2 + d3 * d3;
#pragma unroll
            for (int off = 16; off; off >>= 1)
                q += __shfl_xor_sync(0xffffffffu, q, off);
            const float rstd = rsqrtf(q * (1.0f / 128.0f) + 1e-5f);
            float* op = out + (size_t)(i * NSEQ + j0 + m) * EOUT;
            op[lane]      = d0 * rstd * g0 + b0;
            op[lane + 32] = d1 * rstd * g1 + b1;
            op[lane + 64] = d2 * rstd * g2 + b2;
            op[lane + 96] = d3 * rstd * g3 + b3;
        }
    }
}

// ---------------------------------------------------------------------------
extern "C" void kernel_launch(void* const* d_in, const int* in_sizes, int n_in,
                              void* d_out, int out_size) {
    const float* node   = (const float*)d_in[0];
    const float* edge   = (const float*)d_in[1];
    const float* w_init = (const float*)d_in[2];
    const float* b_init = (const float*)d_in[3];
    const float* w_t0   = (const float*)d_in[4];
    const float* b_t0   = (const float*)d_in[5];
    const float* w_t1   = (const float*)d_in[6];
    const float* b_t1   = (const float*)d_in[7];
    const float* w_fin  = (const float*)d_in[8];
    const float* b_fin  = (const float*)d_in[9];
    const float* ln_g   = (const float*)d_in[10];
    const float* ln_b   = (const float*)d_in[11];
    float* out = (float*)d_out;
    (void)in_sizes; (void)n_in; (void)out_size;

    cudaFuncSetAttribute(fusedh,
                         cudaFuncAttributeMaxDynamicSharedMemorySize, SMEMSZ);

    packh_kernel<<<256, 256>>>(w_t0, w_t1, w_fin);
    nb_kernel<<<NSEQ, 128>>>(node, w_init, b_init);
    pre_kernel<<<NSEQ, HID>>>(w_t0, b_t0, w_fin, b_fin);
    fusedh<<<4096, NTHR, SMEMSZ>>>(edge, b_t1, ln_g, ln_b, out);
}